// round 7
// baseline (speedup 1.0000x reference)
#include <cuda_runtime.h>

#define B_     16
#define N_     50000
#define INC_   128
#define HID_   64
#define NC_    512
#define TOTAL_ (B_ * N_)     // 800000
#define BINS_  (B_ * NC_)    // 8192
#define CAP_   256           // fixed per-bin capacity (mean 97.7, sigma 9.9)
#define NTILES (TOTAL_ / 128)

// ---- scratch (no allocations allowed; __device__ globals, zero-init) ----
__device__ int   g_cursor[BINS_];
__device__ int   g_binidx[BINS_ * CAP_];     // bin bc at [bc<<8 ..]
__device__ float g_segmax[BINS_ * HID_];     // 2 MB, L2-resident

// ---------------------------------------------------------------------------
// bf16 split helper: f = hi + lo (each bf16), packed as bf16x2 (lo half = f0).
// ---------------------------------------------------------------------------
__device__ __forceinline__ void split2(float f0, float f1,
                                       unsigned& hi, unsigned& lo) {
    unsigned h;
    asm("cvt.rn.bf16x2.f32 %0, %1, %2;" : "=r"(h) : "f"(f1), "f"(f0));
    float h0 = __uint_as_float(h << 16);
    float h1 = __uint_as_float(h & 0xffff0000u);
    float r0 = f0 - h0, r1 = f1 - h1;
    unsigned l;
    asm("cvt.rn.bf16x2.f32 %0, %1, %2;" : "=r"(l) : "f"(r1), "f"(r0));
    hi = h; lo = l;
}

#define MMA_BF16(c, a, b0v, b1v)                                              \
    asm volatile(                                                             \
        "mma.sync.aligned.m16n8k16.row.col.f32.bf16.bf16.f32 "                \
        "{%0,%1,%2,%3}, {%4,%5,%6,%7}, {%8,%9}, {%0,%1,%2,%3};"               \
        : "+f"((c)[0]), "+f"((c)[1]), "+f"((c)[2]), "+f"((c)[3])              \
        : "r"((a)[0]), "r"((a)[1]), "r"((a)[2]), "r"((a)[3]),                 \
          "r"(b0v), "r"(b1v))

// ---------------------------------------------------------------------------
// PERSISTENT encode on tensor cores: h = relu(LN(x @ W + b)), bf16x3 split.
// 296 blocks (2/SM) stage W once into smem, then loop over 128-node tiles.
// Eliminates 200MB of per-block W re-staging L2 traffic + 6250 prologues.
// Warp computes a 16-node x 64-col tile via mma.m16n8k16; W rows padded to 65
// words (conflict-free B-frag loads). Fused cursor-scatter per tile.
// LN is quad-local: row stats via two shfl.xor.
// ---------------------------------------------------------------------------
#define PGRID 296

__global__ __launch_bounds__(256, 2) void encode_kernel(
    const float* __restrict__ x, const int* __restrict__ cluster,
    const float* __restrict__ W,
    const float* __restrict__ bias, const float* __restrict__ gamma,
    const float* __restrict__ beta, float* __restrict__ out)
{
    __shared__ unsigned sWhi[64 * 65];   // [k2][n], padded
    __shared__ unsigned sWlo[64 * 65];
    __shared__ float sB[HID_], sG[HID_], sBt[HID_];

    int tid = threadIdx.x;

    // ---- stage W once (packed bf16x2 hi/lo) ----
#pragma unroll
    for (int it = 0; it < 16; it++) {
        int idx = tid + it * 256;              // 4096 packed entries
        int k2 = idx >> 6, n = idx & 63;
        float f0 = W[(2 * k2) * 64 + n];       // coalesced (n contiguous)
        float f1 = W[(2 * k2 + 1) * 64 + n];
        unsigned h, l;
        split2(f0, f1, h, l);
        sWhi[k2 * 65 + n] = h;
        sWlo[k2 * 65 + n] = l;
    }
    if (tid < HID_) { sB[tid] = bias[tid]; sG[tid] = gamma[tid]; sBt[tid] = beta[tid]; }
    __syncthreads();

    int warp = tid >> 5, lane = tid & 31;
    int g = lane >> 2, tig = lane & 3;

    for (int tile = blockIdx.x; tile < NTILES; tile += PGRID) {
        int blockbase = tile * 128;

        // ---- fused scatter (threads 0..127; latency hidden under GEMM) ----
        if (tid < 128) {
            int node = blockbase + tid;
            int b = node / N_;
            int n = node - b * N_;
            int bc = (b << 9) + cluster[node];
            int pos = atomicAdd(&g_cursor[bc], 1);
            g_binidx[(bc << 8) + pos] = n;
        }

        int wb = blockbase + warp * 16;        // warp's first node

        float acc[8][4];
#pragma unroll
        for (int t = 0; t < 8; t++)
#pragma unroll
            for (int c = 0; c < 4; c++) acc[t][c] = 0.f;

        const float2* xr0 = (const float2*)(x + (size_t)(wb + g) * INC_);
        const float2* xr1 = (const float2*)(x + (size_t)(wb + g + 8) * INC_);

#pragma unroll
        for (int kt = 0; kt < 8; kt++) {       // k-tiles of 16
            int k2base = kt * 8;
            float2 f00 = xr0[k2base + tig];
            float2 f10 = xr1[k2base + tig];
            float2 f01 = xr0[k2base + tig + 4];
            float2 f11 = xr1[k2base + tig + 4];

            unsigned ahi[4], alo[4];
            split2(f00.x, f00.y, ahi[0], alo[0]);
            split2(f10.x, f10.y, ahi[1], alo[1]);
            split2(f01.x, f01.y, ahi[2], alo[2]);
            split2(f11.x, f11.y, ahi[3], alo[3]);

            int ra = (k2base + tig) * 65;
            int rb = (k2base + tig + 4) * 65;
#pragma unroll
            for (int t = 0; t < 8; t++) {
                int ncol = t * 8 + g;
                unsigned bh0 = sWhi[ra + ncol], bh1 = sWhi[rb + ncol];
                unsigned bl0 = sWlo[ra + ncol], bl1 = sWlo[rb + ncol];
                MMA_BF16(acc[t], ahi, bh0, bh1);   // hi * Hi
                MMA_BF16(acc[t], ahi, bl0, bl1);   // hi * Lo
                MMA_BF16(acc[t], alo, bh0, bh1);   // lo * Hi
            }
        }

        // ---- epilogue: bias, LN stats (quad-local), relu, store ----
        float s0 = 0.f, q0 = 0.f, s1 = 0.f, q1 = 0.f;
#pragma unroll
        for (int t = 0; t < 8; t++) {
            int n0 = t * 8 + 2 * tig;
            float b0v = sB[n0], b1v = sB[n0 + 1];
            acc[t][0] += b0v; acc[t][1] += b1v;    // row g
            acc[t][2] += b0v; acc[t][3] += b1v;    // row g+8
            s0 += acc[t][0] + acc[t][1];
            q0 = fmaf(acc[t][0], acc[t][0], q0);
            q0 = fmaf(acc[t][1], acc[t][1], q0);
            s1 += acc[t][2] + acc[t][3];
            q1 = fmaf(acc[t][2], acc[t][2], q1);
            q1 = fmaf(acc[t][3], acc[t][3], q1);
        }
#pragma unroll
        for (int w = 1; w <= 2; w <<= 1) {
            s0 += __shfl_xor_sync(0xffffffffu, s0, w);
            q0 += __shfl_xor_sync(0xffffffffu, q0, w);
            s1 += __shfl_xor_sync(0xffffffffu, s1, w);
            q1 += __shfl_xor_sync(0xffffffffu, q1, w);
        }
        float mu0 = s0 * (1.f / 64.f);
        float rs0 = rsqrtf(q0 * (1.f / 64.f) - mu0 * mu0 + 1e-5f);
        float mu1 = s1 * (1.f / 64.f);
        float rs1 = rsqrtf(q1 * (1.f / 64.f) - mu1 * mu1 + 1e-5f);

        float* o0 = out + (size_t)(wb + g) * 128;
        float* o1 = out + (size_t)(wb + g + 8) * 128;
#pragma unroll
        for (int t = 0; t < 8; t++) {
            int n0 = t * 8 + 2 * tig;
            float g0 = sG[n0], g1 = sG[n0 + 1], e0 = sBt[n0], e1 = sBt[n0 + 1];
            float2 v0, v1;
            v0.x = fmaxf(fmaf((acc[t][0] - mu0) * rs0, g0, e0), 0.f);
            v0.y = fmaxf(fmaf((acc[t][1] - mu0) * rs0, g1, e1), 0.f);
            v1.x = fmaxf(fmaf((acc[t][2] - mu1) * rs1, g0, e0), 0.f);
            v1.y = fmaxf(fmaf((acc[t][3] - mu1) * rs1, g1, e1), 0.f);
            *(float2*)(o0 + n0) = v0;
            *(float2*)(o1 + n0) = v1;
        }
    }
}

// ---------------------------------------------------------------------------
// Phase A: segmax only. One block per (batch,cluster): gather member h-rows,
// max-reduce, write the 64-float max row into g_segmax (2MB, stays in L2).
// Resets its own cursor for the next graph replay (zero_kernel eliminated).
// ---------------------------------------------------------------------------
__global__ __launch_bounds__(256) void segmax_kernel(const float* __restrict__ out) {
    int bc  = blockIdx.x;
    int cnt = g_cursor[bc];
    int b   = bc >> 9;
    int e   = threadIdx.x >> 4;
    int d4  = threadIdx.x & 15;

    __shared__ int    sidx[CAP_];
    __shared__ float4 sm[256];

    if (threadIdx.x < cnt) sidx[threadIdx.x] = g_binidx[(bc << 8) + threadIdx.x];
    if (threadIdx.x == 0) g_cursor[bc] = 0;   // reset for next replay
    __syncthreads();

    size_t rowbase = (size_t)b * N_ * 128;

    float4 m = make_float4(-3.402823466e38f, -3.402823466e38f,
                           -3.402823466e38f, -3.402823466e38f);
    for (int i = e; i < cnt; i += 16) {
        int n = sidx[i];
        float4 v = ((const float4*)(out + rowbase + (size_t)n * 128))[d4];
        m.x = fmaxf(m.x, v.x); m.y = fmaxf(m.y, v.y);
        m.z = fmaxf(m.z, v.z); m.w = fmaxf(m.w, v.w);
    }
    sm[threadIdx.x] = m;
    __syncthreads();
#pragma unroll
    for (int off = 128; off >= 16; off >>= 1) {
        if (threadIdx.x < off) {
            float4 a = sm[threadIdx.x], c = sm[threadIdx.x + off];
            a.x = fmaxf(a.x, c.x); a.y = fmaxf(a.y, c.y);
            a.z = fmaxf(a.z, c.z); a.w = fmaxf(a.w, c.w);
            sm[threadIdx.x] = a;
        }
        __syncthreads();
    }
    if (threadIdx.x < 16)
        ((float4*)(g_segmax + bc * HID_))[d4] = sm[d4];
}

// ---------------------------------------------------------------------------
// Phase B: broadcast. Pure streaming: each node reads its cluster's segmax
// row (L2-hot 2MB) and writes out[node][64:128] coalesced. 16 nodes/block.
// ---------------------------------------------------------------------------
__global__ __launch_bounds__(256) void bcast_kernel(
    const int* __restrict__ cluster, float* __restrict__ out)
{
    int node   = blockIdx.x * 16 + (threadIdx.x >> 4);
    int lane16 = threadIdx.x & 15;
    int b = node / N_;
    int c = cluster[node];
    float4 v = ((const float4*)(g_segmax + ((size_t)(b << 9) + c) * HID_))[lane16];
    ((float4*)(out + (size_t)node * 128 + 64))[lane16] = v;
}

// ---------------------------------------------------------------------------
extern "C" void kernel_launch(void* const* d_in, const int* in_sizes, int n_in,
                              void* d_out, int out_size) {
    const float* x       = (const float*)d_in[0];
    const int*   cluster = (const int*)  d_in[1];
    const float* W       = (const float*)d_in[2];
    const float* bias    = (const float*)d_in[3];
    const float* gamma   = (const float*)d_in[4];
    const float* beta    = (const float*)d_in[5];
    float* out = (float*)d_out;

    encode_kernel<<<PGRID, 256>>>(x, cluster, W, bias, gamma, beta, out);
    segmax_kernel<<<BINS_, 256>>>(out);
    bcast_kernel<<<TOTAL_ / 16, 256>>>(cluster, out);
}

// round 9
// speedup vs baseline: 1.1856x; 1.1856x over previous
#include <cuda_runtime.h>

#define B_     16
#define N_     50000
#define INC_   128
#define HID_   64
#define NC_    512
#define TOTAL_ (B_ * N_)     // 800000
#define BINS_  (B_ * NC_)    // 8192
#define CAP_   256           // fixed per-bin capacity (mean 97.7, sigma 9.9)
#define NTILES (TOTAL_ / 128)
#define WPITCH 72            // smem row pitch (words): 72 ≡ 8 (mod 32) ->
                             // bank = 8*tig + g, a perfect 32-bank permutation

// ---- scratch (no allocations allowed; __device__ globals, zero-init) ----
__device__ int   g_cursor[BINS_];
__device__ int   g_binidx[BINS_ * CAP_];     // bin bc at [bc<<8 ..]
__device__ float g_segmax[BINS_ * HID_];     // 2 MB, L2-resident

// ---------------------------------------------------------------------------
// bf16 split helper: f = hi + lo (each bf16), packed as bf16x2 (lo half = f0).
// ---------------------------------------------------------------------------
__device__ __forceinline__ void split2(float f0, float f1,
                                       unsigned& hi, unsigned& lo) {
    unsigned h;
    asm("cvt.rn.bf16x2.f32 %0, %1, %2;" : "=r"(h) : "f"(f1), "f"(f0));
    float h0 = __uint_as_float(h << 16);
    float h1 = __uint_as_float(h & 0xffff0000u);
    float r0 = f0 - h0, r1 = f1 - h1;
    unsigned l;
    asm("cvt.rn.bf16x2.f32 %0, %1, %2;" : "=r"(l) : "f"(r1), "f"(r0));
    hi = h; lo = l;
}

#define MMA_BF16(c, a, b0v, b1v)                                              \
    asm volatile(                                                             \
        "mma.sync.aligned.m16n8k16.row.col.f32.bf16.bf16.f32 "                \
        "{%0,%1,%2,%3}, {%4,%5,%6,%7}, {%8,%9}, {%0,%1,%2,%3};"               \
        : "+f"((c)[0]), "+f"((c)[1]), "+f"((c)[2]), "+f"((c)[3])              \
        : "r"((a)[0]), "r"((a)[1]), "r"((a)[2]), "r"((a)[3]),                 \
          "r"(b0v), "r"(b1v))

// ---------------------------------------------------------------------------
// PERSISTENT encode on tensor cores: h = relu(LN(x @ W + b)), bf16x3 split.
// 296 blocks (2/SM) stage W once into smem, then loop over 128-node tiles.
// B-fragment smem rows use pitch 72 (bank-conflict-FREE: the old pitch 65
// gave bank=(tig+g)%32 -> 4-way conflicts and pinned L1 at 90.8%).
// Warp computes a 16-node x 64-col tile via mma.m16n8k16.
// Fused cursor-scatter per tile. LN is quad-local via two shfl.xor.
// ---------------------------------------------------------------------------
#define PGRID 296

__global__ __launch_bounds__(256, 2) void encode_kernel(
    const float* __restrict__ x, const int* __restrict__ cluster,
    const float* __restrict__ W,
    const float* __restrict__ bias, const float* __restrict__ gamma,
    const float* __restrict__ beta, float* __restrict__ out)
{
    __shared__ unsigned sWhi[64 * WPITCH];   // [k2][n], pitch 72
    __shared__ unsigned sWlo[64 * WPITCH];
    __shared__ float sB[HID_], sG[HID_], sBt[HID_];

    int tid = threadIdx.x;

    // ---- stage W once (packed bf16x2 hi/lo) ----
#pragma unroll
    for (int it = 0; it < 16; it++) {
        int idx = tid + it * 256;              // 4096 packed entries
        int k2 = idx >> 6, n = idx & 63;
        float f0 = W[(2 * k2) * 64 + n];       // coalesced (n contiguous)
        float f1 = W[(2 * k2 + 1) * 64 + n];
        unsigned h, l;
        split2(f0, f1, h, l);
        sWhi[k2 * WPITCH + n] = h;
        sWlo[k2 * WPITCH + n] = l;
    }
    if (tid < HID_) { sB[tid] = bias[tid]; sG[tid] = gamma[tid]; sBt[tid] = beta[tid]; }
    __syncthreads();

    int warp = tid >> 5, lane = tid & 31;
    int g = lane >> 2, tig = lane & 3;

    for (int tile = blockIdx.x; tile < NTILES; tile += PGRID) {
        int blockbase = tile * 128;

        // ---- fused scatter (threads 0..127; latency hidden under GEMM) ----
        if (tid < 128) {
            int node = blockbase + tid;
            int b = node / N_;
            int n = node - b * N_;
            int bc = (b << 9) + cluster[node];
            int pos = atomicAdd(&g_cursor[bc], 1);
            g_binidx[(bc << 8) + pos] = n;
        }

        int wb = blockbase + warp * 16;        // warp's first node

        float acc[8][4];
#pragma unroll
        for (int t = 0; t < 8; t++)
#pragma unroll
            for (int c = 0; c < 4; c++) acc[t][c] = 0.f;

        const float2* xr0 = (const float2*)(x + (size_t)(wb + g) * INC_);
        const float2* xr1 = (const float2*)(x + (size_t)(wb + g + 8) * INC_);

#pragma unroll
        for (int kt = 0; kt < 8; kt++) {       // k-tiles of 16
            int k2base = kt * 8;
            float2 f00 = xr0[k2base + tig];
            float2 f10 = xr1[k2base + tig];
            float2 f01 = xr0[k2base + tig + 4];
            float2 f11 = xr1[k2base + tig + 4];

            unsigned ahi[4], alo[4];
            split2(f00.x, f00.y, ahi[0], alo[0]);
            split2(f10.x, f10.y, ahi[1], alo[1]);
            split2(f01.x, f01.y, ahi[2], alo[2]);
            split2(f11.x, f11.y, ahi[3], alo[3]);

            int ra = (k2base + tig) * WPITCH;
            int rb = (k2base + tig + 4) * WPITCH;
#pragma unroll
            for (int t = 0; t < 8; t++) {
                int ncol = t * 8 + g;
                unsigned bh0 = sWhi[ra + ncol], bh1 = sWhi[rb + ncol];
                unsigned bl0 = sWlo[ra + ncol], bl1 = sWlo[rb + ncol];
                MMA_BF16(acc[t], ahi, bh0, bh1);   // hi * Hi
                MMA_BF16(acc[t], ahi, bl0, bl1);   // hi * Lo
                MMA_BF16(acc[t], alo, bh0, bh1);   // lo * Hi
            }
        }

        // ---- epilogue: bias, LN stats (quad-local), relu, store ----
        float s0 = 0.f, q0 = 0.f, s1 = 0.f, q1 = 0.f;
#pragma unroll
        for (int t = 0; t < 8; t++) {
            int n0 = t * 8 + 2 * tig;
            float b0v = sB[n0], b1v = sB[n0 + 1];
            acc[t][0] += b0v; acc[t][1] += b1v;    // row g
            acc[t][2] += b0v; acc[t][3] += b1v;    // row g+8
            s0 += acc[t][0] + acc[t][1];
            q0 = fmaf(acc[t][0], acc[t][0], q0);
            q0 = fmaf(acc[t][1], acc[t][1], q0);
            s1 += acc[t][2] + acc[t][3];
            q1 = fmaf(acc[t][2], acc[t][2], q1);
            q1 = fmaf(acc[t][3], acc[t][3], q1);
        }
#pragma unroll
        for (int w = 1; w <= 2; w <<= 1) {
            s0 += __shfl_xor_sync(0xffffffffu, s0, w);
            q0 += __shfl_xor_sync(0xffffffffu, q0, w);
            s1 += __shfl_xor_sync(0xffffffffu, s1, w);
            q1 += __shfl_xor_sync(0xffffffffu, q1, w);
        }
        float mu0 = s0 * (1.f / 64.f);
        float rs0 = rsqrtf(q0 * (1.f / 64.f) - mu0 * mu0 + 1e-5f);
        float mu1 = s1 * (1.f / 64.f);
        float rs1 = rsqrtf(q1 * (1.f / 64.f) - mu1 * mu1 + 1e-5f);

        float* o0 = out + (size_t)(wb + g) * 128;
        float* o1 = out + (size_t)(wb + g + 8) * 128;
#pragma unroll
        for (int t = 0; t < 8; t++) {
            int n0 = t * 8 + 2 * tig;
            float g0 = sG[n0], g1 = sG[n0 + 1], e0 = sBt[n0], e1 = sBt[n0 + 1];
            float2 v0, v1;
            v0.x = fmaxf(fmaf((acc[t][0] - mu0) * rs0, g0, e0), 0.f);
            v0.y = fmaxf(fmaf((acc[t][1] - mu0) * rs0, g1, e1), 0.f);
            v1.x = fmaxf(fmaf((acc[t][2] - mu1) * rs1, g0, e0), 0.f);
            v1.y = fmaxf(fmaf((acc[t][3] - mu1) * rs1, g1, e1), 0.f);
            *(float2*)(o0 + n0) = v0;
            *(float2*)(o1 + n0) = v1;
        }
    }
}

// ---------------------------------------------------------------------------
// Phase A: segmax only. One block per (batch,cluster): gather member h-rows,
// max-reduce, write the 64-float max row into g_segmax (2MB, L2-resident).
// RACE FIX: thread 0 alone reads the cursor into smem AND resets it (a
// single-thread read-then-write), then __syncthreads publishes the count.
// The old code let warp 0 reset the cursor before other warps had read it,
// leaving sidx[] partially unstaged -> garbage node index -> illegal access.
// ---------------------------------------------------------------------------
__global__ __launch_bounds__(256) void segmax_kernel(const float* __restrict__ out) {
    int bc = blockIdx.x;
    int b  = bc >> 9;
    int e  = threadIdx.x >> 4;
    int d4 = threadIdx.x & 15;

    __shared__ int    scnt;
    __shared__ int    sidx[CAP_];
    __shared__ float4 sm[256];

    if (threadIdx.x == 0) {
        scnt = g_cursor[bc];      // read-then-reset by ONE thread: race-free
        g_cursor[bc] = 0;         // ready for next graph replay
    }
    __syncthreads();
    int cnt = scnt;

    if (threadIdx.x < cnt) sidx[threadIdx.x] = g_binidx[(bc << 8) + threadIdx.x];
    __syncthreads();

    size_t rowbase = (size_t)b * N_ * 128;

    float4 m = make_float4(-3.402823466e38f, -3.402823466e38f,
                           -3.402823466e38f, -3.402823466e38f);
    for (int i = e; i < cnt; i += 16) {
        int n = sidx[i];
        float4 v = ((const float4*)(out + rowbase + (size_t)n * 128))[d4];
        m.x = fmaxf(m.x, v.x); m.y = fmaxf(m.y, v.y);
        m.z = fmaxf(m.z, v.z); m.w = fmaxf(m.w, v.w);
    }
    sm[threadIdx.x] = m;
    __syncthreads();
#pragma unroll
    for (int off = 128; off >= 16; off >>= 1) {
        if (threadIdx.x < off) {
            float4 a = sm[threadIdx.x], c = sm[threadIdx.x + off];
            a.x = fmaxf(a.x, c.x); a.y = fmaxf(a.y, c.y);
            a.z = fmaxf(a.z, c.z); a.w = fmaxf(a.w, c.w);
            sm[threadIdx.x] = a;
        }
        __syncthreads();
    }
    if (threadIdx.x < 16)
        ((float4*)(g_segmax + bc * HID_))[d4] = sm[d4];
}

// ---------------------------------------------------------------------------
// Phase B: broadcast. Pure streaming: each node reads its cluster's segmax
// row (L2-hot 2MB) and writes out[node][64:128] coalesced. 16 nodes/block.
// ---------------------------------------------------------------------------
__global__ __launch_bounds__(256) void bcast_kernel(
    const int* __restrict__ cluster, float* __restrict__ out)
{
    int node   = blockIdx.x * 16 + (threadIdx.x >> 4);
    int lane16 = threadIdx.x & 15;
    int b = node / N_;
    int c = cluster[node];
    float4 v = ((const float4*)(g_segmax + ((size_t)(b << 9) + c) * HID_))[lane16];
    ((float4*)(out + (size_t)node * 128 + 64))[lane16] = v;
}

// ---------------------------------------------------------------------------
extern "C" void kernel_launch(void* const* d_in, const int* in_sizes, int n_in,
                              void* d_out, int out_size) {
    const float* x       = (const float*)d_in[0];
    const int*   cluster = (const int*)  d_in[1];
    const float* W       = (const float*)d_in[2];
    const float* bias    = (const float*)d_in[3];
    const float* gamma   = (const float*)d_in[4];
    const float* beta    = (const float*)d_in[5];
    float* out = (float*)d_out;

    encode_kernel<<<PGRID, 256>>>(x, cluster, W, bias, gamma, beta, out);
    segmax_kernel<<<BINS_, 256>>>(out);
    bcast_kernel<<<TOTAL_ / 16, 256>>>(cluster, out);
}